// round 1
// baseline (speedup 1.0000x reference)
#include <cuda_runtime.h>
#include <cuda_bf16.h>
#include <math.h>

#define DIM    1024
#define HID    3072
#define MTOK   8192
#define FSCALE (1.0f / 127.0f)

// Scratch (allocation-guard-safe __device__ globals)
__device__ float g_gate[(size_t)MTOK * HID];
__device__ float g_up  [(size_t)MTOK * HID];

// C[M,N] = alpha * A[M,K] @ B[N,K]^T ; B holds int8 values stored as int32.
// BM=BN=128, BK=16, 256 threads, 8x8 per thread with split fragments (+0 / +64).
__global__ __launch_bounds__(256)
void gemm_nt_int8w(const float* __restrict__ A,
                   const int*   __restrict__ B,
                   float* __restrict__ C,
                   int M, int N, int K, float alpha)
{
    __shared__ float As[16][128];
    __shared__ float Bs[16][128];

    const int tid = threadIdx.x;
    const int tx  = tid & 15;   // n-group
    const int ty  = tid >> 4;   // m-group
    const int m0  = blockIdx.y * 128;
    const int n0  = blockIdx.x * 128;

    float acc[8][8];
#pragma unroll
    for (int i = 0; i < 8; ++i)
#pragma unroll
        for (int j = 0; j < 8; ++j) acc[i][j] = 0.0f;

    const int kTiles = K >> 4;
    for (int kt = 0; kt < kTiles; ++kt) {
        const int k0 = kt << 4;

        // Load A tile 128x16 (512 float4, 2 per thread), store transposed As[k][m]
#pragma unroll
        for (int i = 0; i < 2; ++i) {
            int idx = tid * 2 + i;
            int row = idx >> 2;
            int c4  = (idx & 3) << 2;
            float4 v = *reinterpret_cast<const float4*>(
                A + (size_t)(m0 + row) * K + k0 + c4);
            As[c4 + 0][row] = v.x;
            As[c4 + 1][row] = v.y;
            As[c4 + 2][row] = v.z;
            As[c4 + 3][row] = v.w;
        }
        // Load B tile 128x16 ints, convert to float (exact for |v|<=127)
#pragma unroll
        for (int i = 0; i < 2; ++i) {
            int idx = tid * 2 + i;
            int row = idx >> 2;
            int c4  = (idx & 3) << 2;
            int4 w = *reinterpret_cast<const int4*>(
                B + (size_t)(n0 + row) * K + k0 + c4);
            Bs[c4 + 0][row] = (float)w.x;
            Bs[c4 + 1][row] = (float)w.y;
            Bs[c4 + 2][row] = (float)w.z;
            Bs[c4 + 3][row] = (float)w.w;
        }
        __syncthreads();

#pragma unroll
        for (int k = 0; k < 16; ++k) {
            float a[8], b[8];
            *reinterpret_cast<float4*>(a)     = *reinterpret_cast<const float4*>(&As[k][ty * 4]);
            *reinterpret_cast<float4*>(a + 4) = *reinterpret_cast<const float4*>(&As[k][ty * 4 + 64]);
            *reinterpret_cast<float4*>(b)     = *reinterpret_cast<const float4*>(&Bs[k][tx * 4]);
            *reinterpret_cast<float4*>(b + 4) = *reinterpret_cast<const float4*>(&Bs[k][tx * 4 + 64]);
#pragma unroll
            for (int i = 0; i < 8; ++i)
#pragma unroll
                for (int j = 0; j < 8; ++j)
                    acc[i][j] = fmaf(a[i], b[j], acc[i][j]);
        }
        __syncthreads();
    }

    // Epilogue: rows {ty*4+i, 64+ty*4+i}, cols {tx*4+j, 64+tx*4+j}
#pragma unroll
    for (int ih = 0; ih < 2; ++ih) {
#pragma unroll
        for (int i = 0; i < 4; ++i) {
            const int m = m0 + ih * 64 + ty * 4 + i;
#pragma unroll
            for (int jh = 0; jh < 2; ++jh) {
                float4 o;
                o.x = acc[ih * 4 + i][jh * 4 + 0] * alpha;
                o.y = acc[ih * 4 + i][jh * 4 + 1] * alpha;
                o.z = acc[ih * 4 + i][jh * 4 + 2] * alpha;
                o.w = acc[ih * 4 + i][jh * 4 + 3] * alpha;
                *reinterpret_cast<float4*>(
                    C + (size_t)m * N + n0 + jh * 64 + tx * 4) = o;
            }
        }
    }
}

// gate <- silu(gate) * up, in place (gate/up already carry the dequant scale)
__global__ void swiglu_kernel(float* __restrict__ gate,
                              const float* __restrict__ up,
                              size_t n4)
{
    size_t i = (size_t)blockIdx.x * blockDim.x + threadIdx.x;
    if (i < n4) {
        float4 g = reinterpret_cast<float4*>(gate)[i];
        float4 u = reinterpret_cast<const float4*>(up)[i];
        g.x = g.x / (1.0f + expf(-g.x)) * u.x;
        g.y = g.y / (1.0f + expf(-g.y)) * u.y;
        g.z = g.z / (1.0f + expf(-g.z)) * u.z;
        g.w = g.w / (1.0f + expf(-g.w)) * u.w;
        reinterpret_cast<float4*>(gate)[i] = g;
    }
}

extern "C" void kernel_launch(void* const* d_in, const int* in_sizes, int n_in,
                              void* d_out, int out_size)
{
    const float* x  = (const float*)d_in[0];
    const int*   wg = (const int*)d_in[1];
    const int*   wu = (const int*)d_in[2];
    const int*   wd = (const int*)d_in[3];
    float*       out = (float*)d_out;

    const int M = in_sizes[0] / DIM;   // 8192

    float* gate = nullptr;
    float* up   = nullptr;
    cudaGetSymbolAddress((void**)&gate, g_gate);
    cudaGetSymbolAddress((void**)&up,   g_up);

    dim3 block(256);
    dim3 grid1(HID / 128, M / 128);   // (24, 64)
    dim3 grid2(DIM / 128, M / 128);   // (8, 64)

    // gate = SCALE * x @ wg^T ; up = SCALE * x @ wu^T
    gemm_nt_int8w<<<grid1, block>>>(x, wg, gate, M, HID, DIM, FSCALE);
    gemm_nt_int8w<<<grid1, block>>>(x, wu, up,   M, HID, DIM, FSCALE);

    // gate <- silu(gate) * up
    const size_t n4 = (size_t)M * HID / 4;
    swiglu_kernel<<<(unsigned)((n4 + 255) / 256), 256>>>(gate, up, n4);

    // out = SCALE * gate @ wd^T
    gemm_nt_int8w<<<grid2, block>>>(gate, wd, out, M, DIM, HID, FSCALE);
}

// round 3
// speedup vs baseline: 3.8361x; 3.8361x over previous
#include <cuda_runtime.h>
#include <cuda_bf16.h>
#include <math.h>
#include <stdint.h>

#define DIM  1024
#define HID  3072
#define MTOK 8192
#define FSCALE (1.0f/127.0f)

// ---------------- device scratch ----------------
__device__ __align__(16) __nv_bfloat16 g_wg [(size_t)HID*DIM];
__device__ __align__(16) __nv_bfloat16 g_wu [(size_t)HID*DIM];
__device__ __align__(16) __nv_bfloat16 g_wd [(size_t)DIM*HID];
__device__ __align__(16) __nv_bfloat16 g_xhi[(size_t)MTOK*DIM];
__device__ __align__(16) __nv_bfloat16 g_xlo[(size_t)MTOK*DIM];
__device__ __align__(16) __nv_bfloat16 g_hhi[(size_t)MTOK*HID];
__device__ __align__(16) __nv_bfloat16 g_hlo[(size_t)MTOK*HID];

// ---------------- helpers ----------------
__device__ __forceinline__ uint32_t smem_u32(const void* p){
    uint32_t a;
    asm("{ .reg .u64 t; cvta.to.shared.u64 t, %1; cvt.u32.u64 %0, t; }" : "=r"(a) : "l"(p));
    return a;
}
__device__ __forceinline__ void cp_async16(uint32_t s, const void* g){
    asm volatile("cp.async.cg.shared.global [%0], [%1], 16;" :: "r"(s), "l"(g));
}
#define CP_COMMIT() asm volatile("cp.async.commit_group;" ::: "memory")
#define CP_WAIT(N)  asm volatile("cp.async.wait_group %0;" :: "n"(N) : "memory")

__device__ __forceinline__ void ldsm_x4(uint32_t* r, uint32_t a){
    asm volatile("ldmatrix.sync.aligned.m8n8.x4.shared.b16 {%0,%1,%2,%3}, [%4];"
        : "=r"(r[0]),"=r"(r[1]),"=r"(r[2]),"=r"(r[3]) : "r"(a));
}
__device__ __forceinline__ void mma16816(float* d, const uint32_t* a, const uint32_t* b){
    asm volatile("mma.sync.aligned.m16n8k16.row.col.f32.bf16.bf16.f32 "
        "{%0,%1,%2,%3},{%4,%5,%6,%7},{%8,%9},{%0,%1,%2,%3};"
        : "+f"(d[0]),"+f"(d[1]),"+f"(d[2]),"+f"(d[3])
        : "r"(a[0]),"r"(a[1]),"r"(a[2]),"r"(a[3]), "r"(b[0]),"r"(b[1]));
}

// ---------------- prep kernels ----------------
__global__ void k_convw(const int* __restrict__ w, __nv_bfloat16* __restrict__ o, int n4){
    int i = blockIdx.x * blockDim.x + threadIdx.x;
    if (i < n4){
        int4 v = ((const int4*)w)[i];
        __nv_bfloat162 a, b;
        a.x = __float2bfloat16((float)v.x); a.y = __float2bfloat16((float)v.y);
        b.x = __float2bfloat16((float)v.z); b.y = __float2bfloat16((float)v.w);
        ((__nv_bfloat162*)o)[2*i]   = a;
        ((__nv_bfloat162*)o)[2*i+1] = b;
    }
}
__global__ void k_splitx(const float* __restrict__ x, __nv_bfloat16* __restrict__ hi,
                         __nv_bfloat16* __restrict__ lo, int n4){
    int i = blockIdx.x * blockDim.x + threadIdx.x;
    if (i < n4){
        float4 v = ((const float4*)x)[i];
        __nv_bfloat162 h0, h1, l0, l1;
        h0.x = __float2bfloat16(v.x); h0.y = __float2bfloat16(v.y);
        h1.x = __float2bfloat16(v.z); h1.y = __float2bfloat16(v.w);
        l0.x = __float2bfloat16(v.x - __bfloat162float(h0.x));
        l0.y = __float2bfloat16(v.y - __bfloat162float(h0.y));
        l1.x = __float2bfloat16(v.z - __bfloat162float(h1.x));
        l1.y = __float2bfloat16(v.w - __bfloat162float(h1.y));
        ((__nv_bfloat162*)hi)[2*i]   = h0; ((__nv_bfloat162*)hi)[2*i+1] = h1;
        ((__nv_bfloat162*)lo)[2*i]   = l0; ((__nv_bfloat162*)lo)[2*i+1] = l1;
    }
}

// ---------------- GEMM1: fused gate/up + SwiGLU ----------------
// CTA tile: M=128, N=128 (gate) + 128 (up). 512 threads = 16 warps (4x4).
// Warp tile: 32(m) x [32 gate + 32 up]. BK=32, 4-stage cp.async pipeline.
static constexpr int ROWB  = 80;        // padded bf16 row bytes (64 data + 16 pad)
static constexpr int AHI_O = 0;
static constexpr int ALO_O = 128*ROWB;          // 10240
static constexpr int B_O   = 2*128*ROWB;        // 20480
static constexpr int STG1  = B_O + 256*ROWB;    // 40960
static constexpr int STG3  = B_O + 128*ROWB;    // 30720
static constexpr int NST   = 4;

__global__ __launch_bounds__(512,1)
void k_gateup(const __nv_bfloat16* __restrict__ xhi, const __nv_bfloat16* __restrict__ xlo,
              const __nv_bfloat16* __restrict__ wg,  const __nv_bfloat16* __restrict__ wu,
              __nv_bfloat16* __restrict__ hhi, __nv_bfloat16* __restrict__ hlo)
{
    extern __shared__ char sm[];
    const uint32_t sb = smem_u32(sm);
    const int tid = threadIdx.x, lane = tid & 31, wid = tid >> 5;
    const int wm = wid >> 2, wn = wid & 3;
    const int m0 = blockIdx.y * 128, n0 = blockIdx.x * 128;

    // per-thread cp.async descriptors (4 chunks of 16B per stage)
    const __nv_bfloat16* gptr[4];
    uint32_t soff[4];
    #pragma unroll
    for (int j = 0; j < 4; ++j){
        int c = j*512 + tid;
        int row = c >> 2, seg = c & 3;
        const __nv_bfloat16* gp; uint32_t so;
        if (row < 128)      { gp = xhi + (size_t)(m0+row)*DIM;     so = AHI_O + row*ROWB; }
        else if (row < 256) { gp = xlo + (size_t)(m0+row-128)*DIM; so = ALO_O + (row-128)*ROWB; }
        else if (row < 384) { gp = wg  + (size_t)(n0+row-256)*DIM; so = B_O   + (row-256)*ROWB; }
        else                { gp = wu  + (size_t)(n0+row-384)*DIM; so = B_O   + (row-256)*ROWB; }
        gptr[j] = gp + seg*8;
        soff[j] = so + seg*16;
    }
    auto load_stage = [&](int s){
        uint32_t st = sb + (uint32_t)(s & (NST-1)) * STG1;
        int k0 = s * 32;
        #pragma unroll
        for (int j = 0; j < 4; ++j) cp_async16(st + soff[j], gptr[j] + k0);
    };

    float accg[2][4][4], accu[2][4][4];
    #pragma unroll
    for (int a = 0; a < 2; ++a)
    #pragma unroll
    for (int b = 0; b < 4; ++b)
    #pragma unroll
    for (int c = 0; c < 4; ++c){ accg[a][b][c] = 0.f; accu[a][b][c] = 0.f; }

    load_stage(0); CP_COMMIT();
    load_stage(1); CP_COMMIT();
    load_stage(2); CP_COMMIT();

    const int arow  = lane & 15;
    const int abyte = (lane >> 4) * 16;
    const int brow  = ((lane >> 4) & 1) * 8 + (lane & 7);
    const int bbyte = ((lane >> 3) & 1) * 16;

    const int S = DIM / 32;   // 32
    for (int s = 0; s < S; ++s){
        CP_WAIT(2);
        __syncthreads();
        if (s + 3 < S) load_stage(s + 3);
        CP_COMMIT();

        uint32_t st = sb + (uint32_t)(s & (NST-1)) * STG1;
        #pragma unroll
        for (int ks = 0; ks < 2; ++ks){
            uint32_t ah[2][4], al[2][4];
            #pragma unroll
            for (int mt = 0; mt < 2; ++mt){
                uint32_t aaddr = st + (uint32_t)((wm*32 + mt*16 + arow)*ROWB + ks*32 + abyte);
                ldsm_x4(ah[mt], aaddr);
                ldsm_x4(al[mt], aaddr + (ALO_O - AHI_O));
            }
            uint32_t bg[4][2], bu[4][2];
            #pragma unroll
            for (int p = 0; p < 2; ++p){
                uint32_t baddr = st + B_O + (uint32_t)((wn*32 + p*16 + brow)*ROWB + ks*32 + bbyte);
                uint32_t t[4];
                ldsm_x4(t, baddr);
                bg[2*p][0]=t[0]; bg[2*p][1]=t[1]; bg[2*p+1][0]=t[2]; bg[2*p+1][1]=t[3];
                ldsm_x4(t, baddr + 128*ROWB);
                bu[2*p][0]=t[0]; bu[2*p][1]=t[1]; bu[2*p+1][0]=t[2]; bu[2*p+1][1]=t[3];
            }
            #pragma unroll
            for (int mt = 0; mt < 2; ++mt)
            #pragma unroll
            for (int nt = 0; nt < 4; ++nt){
                mma16816(accg[mt][nt], ah[mt], bg[nt]);
                mma16816(accg[mt][nt], al[mt], bg[nt]);
                mma16816(accu[mt][nt], ah[mt], bu[nt]);
                mma16816(accu[mt][nt], al[mt], bu[nt]);
            }
        }
    }

    // epilogue: h = silu(gate)*up, split hi/lo bf16
    const int g = lane >> 2, tig = lane & 3;
    #pragma unroll
    for (int mt = 0; mt < 2; ++mt){
        int rb = m0 + wm*32 + mt*16 + g;
        #pragma unroll
        for (int nt = 0; nt < 4; ++nt){
            int col = n0 + wn*32 + nt*8 + tig*2;
            #pragma unroll
            for (int rr = 0; rr < 2; ++rr){
                int r = rb + rr*8;
                float g0 = accg[mt][nt][rr*2+0] * FSCALE;
                float g1 = accg[mt][nt][rr*2+1] * FSCALE;
                float u0 = accu[mt][nt][rr*2+0] * FSCALE;
                float u1 = accu[mt][nt][rr*2+1] * FSCALE;
                float h0 = g0 / (1.0f + expf(-g0)) * u0;
                float h1 = g1 / (1.0f + expf(-g1)) * u1;
                __nv_bfloat162 ph, pl;
                ph.x = __float2bfloat16(h0); ph.y = __float2bfloat16(h1);
                pl.x = __float2bfloat16(h0 - __bfloat162float(ph.x));
                pl.y = __float2bfloat16(h1 - __bfloat162float(ph.y));
                *(__nv_bfloat162*)(hhi + (size_t)r*HID + col) = ph;
                *(__nv_bfloat162*)(hlo + (size_t)r*HID + col) = pl;
            }
        }
    }
}

// ---------------- GEMM3: out = SCALE * h @ Wd^T ----------------
// CTA tile 128x128, warp tile 32x32, BK=32, K=HID.
__global__ __launch_bounds__(512,1)
void k_down(const __nv_bfloat16* __restrict__ ahi, const __nv_bfloat16* __restrict__ alo,
            const __nv_bfloat16* __restrict__ wd, float* __restrict__ out)
{
    extern __shared__ char sm[];
    const uint32_t sb = smem_u32(sm);
    const int tid = threadIdx.x, lane = tid & 31, wid = tid >> 5;
    const int wm = wid >> 2, wn = wid & 3;
    const int m0 = blockIdx.y * 128, n0 = blockIdx.x * 128;

    const __nv_bfloat16* gptr[3];
    uint32_t soff[3];
    #pragma unroll
    for (int j = 0; j < 3; ++j){
        int c = j*512 + tid;
        int row = c >> 2, seg = c & 3;
        const __nv_bfloat16* gp; uint32_t so;
        if (row < 128)      { gp = ahi + (size_t)(m0+row)*HID;     so = AHI_O + row*ROWB; }
        else if (row < 256) { gp = alo + (size_t)(m0+row-128)*HID; so = ALO_O + (row-128)*ROWB; }
        else                { gp = wd  + (size_t)(n0+row-256)*HID; so = B_O   + (row-256)*ROWB; }
        gptr[j] = gp + seg*8;
        soff[j] = so + seg*16;
    }
    auto load_stage = [&](int s){
        uint32_t st = sb + (uint32_t)(s & (NST-1)) * STG3;
        int k0 = s * 32;
        #pragma unroll
        for (int j = 0; j < 3; ++j) cp_async16(st + soff[j], gptr[j] + k0);
    };

    float acc[2][4][4];
    #pragma unroll
    for (int a = 0; a < 2; ++a)
    #pragma unroll
    for (int b = 0; b < 4; ++b)
    #pragma unroll
    for (int c = 0; c < 4; ++c) acc[a][b][c] = 0.f;

    load_stage(0); CP_COMMIT();
    load_stage(1); CP_COMMIT();
    load_stage(2); CP_COMMIT();

    const int arow  = lane & 15;
    const int abyte = (lane >> 4) * 16;
    const int brow  = ((lane >> 4) & 1) * 8 + (lane & 7);
    const int bbyte = ((lane >> 3) & 1) * 16;

    const int S = HID / 32;   // 96
    for (int s = 0; s < S; ++s){
        CP_WAIT(2);
        __syncthreads();
        if (s + 3 < S) load_stage(s + 3);
        CP_COMMIT();

        uint32_t st = sb + (uint32_t)(s & (NST-1)) * STG3;
        #pragma unroll
        for (int ks = 0; ks < 2; ++ks){
            uint32_t ah[2][4], al[2][4];
            #pragma unroll
            for (int mt = 0; mt < 2; ++mt){
                uint32_t aaddr = st + (uint32_t)((wm*32 + mt*16 + arow)*ROWB + ks*32 + abyte);
                ldsm_x4(ah[mt], aaddr);
                ldsm_x4(al[mt], aaddr + (ALO_O - AHI_O));
            }
            uint32_t bw[4][2];
            #pragma unroll
            for (int p = 0; p < 2; ++p){
                uint32_t baddr = st + B_O + (uint32_t)((wn*32 + p*16 + brow)*ROWB + ks*32 + bbyte);
                uint32_t t[4];
                ldsm_x4(t, baddr);
                bw[2*p][0]=t[0]; bw[2*p][1]=t[1]; bw[2*p+1][0]=t[2]; bw[2*p+1][1]=t[3];
            }
            #pragma unroll
            for (int mt = 0; mt < 2; ++mt)
            #pragma unroll
            for (int nt = 0; nt < 4; ++nt){
                mma16816(acc[mt][nt], ah[mt], bw[nt]);
                mma16816(acc[mt][nt], al[mt], bw[nt]);
            }
        }
    }

    const int g = lane >> 2, tig = lane & 3;
    #pragma unroll
    for (int mt = 0; mt < 2; ++mt){
        int rb = m0 + wm*32 + mt*16 + g;
        #pragma unroll
        for (int nt = 0; nt < 4; ++nt){
            int col = n0 + wn*32 + nt*8 + tig*2;
            #pragma unroll
            for (int rr = 0; rr < 2; ++rr){
                int r = rb + rr*8;
                float2 o;
                o.x = acc[mt][nt][rr*2+0] * FSCALE;
                o.y = acc[mt][nt][rr*2+1] * FSCALE;
                *(float2*)(out + (size_t)r*DIM + col) = o;
            }
        }
    }
}

// ---------------- launch ----------------
extern "C" void kernel_launch(void* const* d_in, const int* in_sizes, int n_in,
                              void* d_out, int out_size)
{
    const float* x  = (const float*)d_in[0];
    const int*   wg = (const int*)d_in[1];
    const int*   wu = (const int*)d_in[2];
    const int*   wd = (const int*)d_in[3];
    float*       out = (float*)d_out;

    const int M = in_sizes[0] / DIM;   // 8192

    __nv_bfloat16 *wgb, *wub, *wdb, *xhi, *xlo, *hhi, *hlo;
    cudaGetSymbolAddress((void**)&wgb, g_wg);
    cudaGetSymbolAddress((void**)&wub, g_wu);
    cudaGetSymbolAddress((void**)&wdb, g_wd);
    cudaGetSymbolAddress((void**)&xhi, g_xhi);
    cudaGetSymbolAddress((void**)&xlo, g_xlo);
    cudaGetSymbolAddress((void**)&hhi, g_hhi);
    cudaGetSymbolAddress((void**)&hlo, g_hlo);

    {
        int n4 = (HID * DIM) / 4;
        k_convw<<<(n4 + 255) / 256, 256>>>(wg, wgb, n4);
        k_convw<<<(n4 + 255) / 256, 256>>>(wu, wub, n4);
        k_convw<<<(n4 + 255) / 256, 256>>>(wd, wdb, n4);
        int nx4 = (M * DIM) / 4;
        k_splitx<<<(nx4 + 255) / 256, 256>>>(x, xhi, xlo, nx4);
    }

    const int SM1 = NST * STG1;   // 163840
    const int SM3 = NST * STG3;   // 122880
    cudaFuncSetAttribute(k_gateup, cudaFuncAttributeMaxDynamicSharedMemorySize, SM1);
    cudaFuncSetAttribute(k_down,   cudaFuncAttributeMaxDynamicSharedMemorySize, SM3);

    dim3 g1(HID / 128, M / 128);   // (24, 64)
    k_gateup<<<g1, 512, SM1>>>(xhi, xlo, wgb, wub, hhi, hlo);

    dim3 g3(DIM / 128, M / 128);   // (8, 64)
    k_down<<<g3, 512, SM3>>>(hhi, hlo, wdb, out);
}